// round 1
// baseline (speedup 1.0000x reference)
#include <cuda_runtime.h>
#include <cuda_bf16.h>
#include <math.h>

// Problem constants
#define BB 2
#define SS 2048
#define DD 1024
#define HH 16
#define DK 64
#define MM (BB*SS)   // 4096 rows

// Scratch (device globals: allocation-free)
__device__ float g_Q[BB*SS*DD];
__device__ float g_K[BB*SS*DD];
__device__ float g_V[BB*SS*DD];
__device__ float g_A[BB*SS*DD];   // attention output (pre-Wo)

// ---------------------------------------------------------------------------
// Classic fp32 SGEMM: C[M,N] = A[M,K] * B[K,N], row-major, 128x128 tile, K=8
// M,N multiples of 128; K multiple of 8. 256 threads, 8x8 per thread.
// ---------------------------------------------------------------------------
__global__ __launch_bounds__(256) void sgemm128(
    const float* __restrict__ A, const float* __restrict__ B,
    float* __restrict__ C, int M, int N, int K)
{
    __shared__ float As[8][128];
    __shared__ float Bs[8][128];

    const int tid = threadIdx.x;
    const int bm = blockIdx.y * 128;
    const int bn = blockIdx.x * 128;

    // A tile load: 128 rows x 8 cols -> one float4 per thread
    const int ar = tid >> 1;          // 0..127
    const int ac = (tid & 1) * 4;     // 0 or 4
    // B tile load: 8 rows x 128 cols -> one float4 per thread
    const int br = tid >> 5;          // 0..7
    const int bc = (tid & 31) * 4;    // 0..124

    const float* Ap = A + (size_t)(bm + ar) * K + ac;
    const float* Bp = B + (size_t)br * N + bn + bc;

    const int tm = (tid >> 4) * 8;    // 0..120
    const int tn = (tid & 15) * 8;    // 0..120

    float acc[8][8];
#pragma unroll
    for (int i = 0; i < 8; i++)
#pragma unroll
        for (int j = 0; j < 8; j++) acc[i][j] = 0.f;

    for (int k0 = 0; k0 < K; k0 += 8) {
        float4 av = *(const float4*)Ap;  Ap += 8;
        float4 bv = *(const float4*)Bp;  Bp += (size_t)8 * N;

        As[ac + 0][ar] = av.x;
        As[ac + 1][ar] = av.y;
        As[ac + 2][ar] = av.z;
        As[ac + 3][ar] = av.w;
        *(float4*)&Bs[br][bc] = bv;
        __syncthreads();

#pragma unroll
        for (int k = 0; k < 8; k++) {
            float a[8], b[8];
            *(float4*)(a)     = *(const float4*)&As[k][tm];
            *(float4*)(a + 4) = *(const float4*)&As[k][tm + 4];
            *(float4*)(b)     = *(const float4*)&Bs[k][tn];
            *(float4*)(b + 4) = *(const float4*)&Bs[k][tn + 4];
#pragma unroll
            for (int i = 0; i < 8; i++)
#pragma unroll
                for (int j = 0; j < 8; j++)
                    acc[i][j] = fmaf(a[i], b[j], acc[i][j]);
        }
        __syncthreads();
    }

#pragma unroll
    for (int i = 0; i < 8; i++) {
        float* cp = C + (size_t)(bm + tm + i) * N + bn + tn;
        *(float4*)(cp)     = *(float4*)&acc[i][0];
        *(float4*)(cp + 4) = *(float4*)&acc[i][4];
    }
}

// ---------------------------------------------------------------------------
// Causal flash attention, fp32.
// grid: (S/BM, B*H), block: BM threads. One thread = one query row.
// Q/K/V stored [B,S,D] with head h at column offset h*DK.
// ---------------------------------------------------------------------------
#define FBM 128
#define FBN 32

__global__ __launch_bounds__(FBM) void flash_attn()
{
    __shared__ float Kb[FBN][DK];
    __shared__ float Vb[FBN][DK];

    const int tid = threadIdx.x;
    const int qb  = blockIdx.x;
    const int bh  = blockIdx.y;
    const int b   = bh / HH;
    const int h   = bh % HH;

    const int row = qb * FBM + tid;
    const float* qptr = g_Q + ((size_t)(b * SS + row)) * DD + h * DK;

    float q[DK];
#pragma unroll
    for (int i = 0; i < DK / 4; i++) {
        float4 v = ((const float4*)qptr)[i];
        q[4*i+0] = v.x; q[4*i+1] = v.y; q[4*i+2] = v.z; q[4*i+3] = v.w;
    }

    float acc[DK];
#pragma unroll
    for (int d = 0; d < DK; d++) acc[d] = 0.f;
    float m = -INFINITY;
    float l = 0.f;

    const int kend = qb * FBM + FBM;   // exclusive: max key index needed + 1

    for (int ks = 0; ks < kend; ks += FBN) {
        // Stage K,V block (FBN rows x DK cols) into shared memory
        for (int idx = tid; idx < FBN * (DK / 4); idx += FBM) {
            const int r = idx >> 4;       // DK/4 == 16 float4 per row
            const int c = idx & 15;
            const size_t g = ((size_t)(b * SS + ks + r)) * DD + h * DK;
            ((float4*)&Kb[r][0])[c] = ((const float4*)(g_K + g))[c];
            ((float4*)&Vb[r][0])[c] = ((const float4*)(g_V + g))[c];
        }
        __syncthreads();

        // Scores for this block
        float s[FBN];
#pragma unroll 4
        for (int j = 0; j < FBN; j++) {
            float a = 0.f;
            const float4* kr = (const float4*)&Kb[j][0];
#pragma unroll
            for (int d4 = 0; d4 < DK / 4; d4++) {
                float4 kv = kr[d4];
                a = fmaf(q[4*d4+0], kv.x, a);
                a = fmaf(q[4*d4+1], kv.y, a);
                a = fmaf(q[4*d4+2], kv.z, a);
                a = fmaf(q[4*d4+3], kv.w, a);
            }
            s[j] = (ks + j <= row) ? a * 0.125f : -INFINITY;  // /sqrt(64)
        }

        float bmax = s[0];
#pragma unroll
        for (int j = 1; j < FBN; j++) bmax = fmaxf(bmax, s[j]);

        const float mn = fmaxf(m, bmax);
        const float corr = __expf(m - mn);   // m finite after first block
        l *= corr;
#pragma unroll
        for (int d = 0; d < DK; d++) acc[d] *= corr;

#pragma unroll 2
        for (int j = 0; j < FBN; j++) {
            const float p = __expf(s[j] - mn);
            l += p;
            const float4* vr = (const float4*)&Vb[j][0];
#pragma unroll
            for (int d4 = 0; d4 < DK / 4; d4++) {
                float4 vv = vr[d4];
                acc[4*d4+0] = fmaf(p, vv.x, acc[4*d4+0]);
                acc[4*d4+1] = fmaf(p, vv.y, acc[4*d4+1]);
                acc[4*d4+2] = fmaf(p, vv.z, acc[4*d4+2]);
                acc[4*d4+3] = fmaf(p, vv.w, acc[4*d4+3]);
            }
        }
        m = mn;
        __syncthreads();
    }

    const float inv = 1.f / l;
    float* op = g_A + ((size_t)(b * SS + row)) * DD + h * DK;
#pragma unroll
    for (int d4 = 0; d4 < DK / 4; d4++) {
        float4 v;
        v.x = acc[4*d4+0] * inv;
        v.y = acc[4*d4+1] * inv;
        v.z = acc[4*d4+2] * inv;
        v.w = acc[4*d4+3] * inv;
        ((float4*)op)[d4] = v;
    }
}

// ---------------------------------------------------------------------------
extern "C" void kernel_launch(void* const* d_in, const int* in_sizes, int n_in,
                              void* d_out, int out_size)
{
    const float* x  = (const float*)d_in[0];
    const float* Wq = (const float*)d_in[1];
    const float* Wk = (const float*)d_in[2];
    const float* Wv = (const float*)d_in[3];
    const float* Wo = (const float*)d_in[4];
    float* out = (float*)d_out;

    float *Qp, *Kp, *Vp, *Ap;
    cudaGetSymbolAddress((void**)&Qp, g_Q);
    cudaGetSymbolAddress((void**)&Kp, g_K);
    cudaGetSymbolAddress((void**)&Vp, g_V);
    cudaGetSymbolAddress((void**)&Ap, g_A);

    dim3 gg(DD / 128, MM / 128);
    sgemm128<<<gg, 256>>>(x, Wq, Qp, MM, DD, DD);
    sgemm128<<<gg, 256>>>(x, Wk, Kp, MM, DD, DD);
    sgemm128<<<gg, 256>>>(x, Wv, Vp, MM, DD, DD);

    dim3 fg(SS / FBM, BB * HH);
    flash_attn<<<fg, FBM>>>();

    sgemm128<<<gg, 256>>>(Ap, Wo, out, MM, DD, DD);
}